// round 13
// baseline (speedup 1.0000x reference)
#include <cuda_runtime.h>
#include <cuda_bf16.h>
#include <math.h>
#include <stdint.h>

// ---------------- problem constants ----------------
#define BB    2
#define LL    2048
#define DD    256
#define DIN   512
#define NH    8
#define NST   64
#define CDIM  640
#define NPROJ 1160
#define ROWS  (BB*LL)      // 4096
#define NC    32           // chunks per sequence
#define QC    64           // chunk length

typedef __nv_bfloat16 bf16;

// ---------------- scratch ----------------
__device__ __align__(16) bf16  g_xh    [ROWS*DD];
__device__ __align__(16) bf16  g_xl    [ROWS*DD];
__device__ __align__(16) float g_zx    [ROWS*NPROJ];
__device__ __align__(16) float g_xact  [ROWS*DIN];
__device__ __align__(16) bf16  g_Bmh   [ROWS*NST];
__device__ __align__(16) bf16  g_Bml   [ROWS*NST];
__device__ __align__(16) bf16  g_Cmh   [ROWS*NST];
__device__ __align__(16) bf16  g_Cml   [ROWS*NST];
__device__ __align__(16) float g_dt    [ROWS*NH];
__device__ __align__(16) float g_dlog  [ROWS*NH];
__device__ __align__(16) float g_chunkS[BB*NH*NC*QC*NST];
__device__ __align__(16) float g_lend  [BB*NH*NC];
__device__ __align__(16) bf16  g_Sinh  [BB*NH*NC*QC*NST];
__device__ __align__(16) bf16  g_Sinl  [BB*NH*NC*QC*NST];
__device__ __align__(16) float g_y     [ROWS*DIN];
__device__ __align__(16) bf16  g_yh    [ROWS*DIN];
__device__ __align__(16) bf16  g_yl    [ROWS*DIN];
__device__ __align__(16) bf16  g_WinTh [1280*DD];           // [n][k], N padded
__device__ __align__(16) bf16  g_WinTl [1280*DD];
__device__ __align__(16) bf16  g_WoutTh[DD*DIN];
__device__ __align__(16) bf16  g_WoutTl[DD*DIN];

__device__ __forceinline__ float fsilu(float x) {
    return __fdividef(x, 1.f + __expf(-x));
}

// ================= warp MMA helpers =================
__device__ __forceinline__ void mma16816(float* c, const uint32_t* a, const uint32_t* b) {
    asm volatile(
        "mma.sync.aligned.m16n8k16.row.col.f32.bf16.bf16.f32 "
        "{%0,%1,%2,%3}, {%4,%5,%6,%7}, {%8,%9}, {%0,%1,%2,%3};"
        : "+f"(c[0]), "+f"(c[1]), "+f"(c[2]), "+f"(c[3])
        : "r"(a[0]), "r"(a[1]), "r"(a[2]), "r"(a[3]), "r"(b[0]), "r"(b[1]));
}
__device__ __forceinline__ uint32_t pk(float a, float b) {
    __nv_bfloat162 t = __floats2bfloat162_rn(a, b);
    return *reinterpret_cast<uint32_t*>(&t);
}
__device__ __forceinline__ float rtbf(float v) {
    return __bfloat162float(__float2bfloat16(v));
}
__device__ __forceinline__ void store4T(bf16* sh, bf16* slo, int q4, int j, float4 v) {
    float f[4] = {v.x, v.y, v.z, v.w};
    #pragma unroll
    for (int k = 0; k < 4; k++) {
        float hi = rtbf(f[k]);
        sh [(q4 + k) * 72 + j] = __float2bfloat16(hi);
        slo[(q4 + k) * 72 + j] = __float2bfloat16(f[k] - hi);
    }
}
__device__ __forceinline__ void lda(uint32_t* a, const bf16* s, int r0, int c) {
    int o0 = r0 * 72 + c, o8 = o0 + 8 * 72;
    a[0] = *(const uint32_t*)(s + o0);
    a[1] = *(const uint32_t*)(s + o8);
    a[2] = *(const uint32_t*)(s + o0 + 8);
    a[3] = *(const uint32_t*)(s + o8 + 8);
}
__device__ __forceinline__ void ldb(uint32_t* b, const bf16* s, int n, int c) {
    int o = n * 72 + c;
    b[0] = *(const uint32_t*)(s + o);
    b[1] = *(const uint32_t*)(s + o + 8);
}
__device__ __forceinline__ void cpasync16(uint32_t saddr, const void* g) {
    asm volatile("cp.async.cg.shared.global [%0], [%1], 16;" :: "r"(saddr), "l"(g));
}
#define CP_COMMIT()  asm volatile("cp.async.commit_group;")
#define CP_WAIT(n)   asm volatile("cp.async.wait_group %0;" :: "n"(n))

// ---------------- K0: transpose + hi/lo split of weights ----------------
__global__ void k_prep(const float* __restrict__ W, bf16* __restrict__ Th,
                       bf16* __restrict__ Tl, int K, int N, int Npad) {
    __shared__ float t[32][33];
    int n0 = blockIdx.x * 32, k0 = blockIdx.y * 32;
    int tx = threadIdx.x, ty = threadIdx.y;
    #pragma unroll
    for (int i = 0; i < 4; i++) {
        int k = k0 + ty + i * 8;
        t[ty + i * 8][tx] = (n0 + tx < N) ? W[(size_t)k * N + n0 + tx] : 0.f;
    }
    __syncthreads();
    #pragma unroll
    for (int i = 0; i < 4; i++) {
        int n = n0 + ty + i * 8;
        if (n < Npad) {
            float v = t[tx][ty + i * 8];
            float hi = rtbf(v);
            Th[(size_t)n * K + k0 + tx] = __float2bfloat16(hi);
            Tl[(size_t)n * K + k0 + tx] = __float2bfloat16(v - hi);
        }
    }
}

// ======== pipelined GEMM (r7 config: K-panel 64, stride 72) ========
#define P_AH 0
#define P_AL (128*72)
#define P_BH (2*128*72)
#define P_BL (2*128*72 + 64*72)
#define P_ELEMS (2*128*72 + 2*64*72)
#define TG_DSMEM (2 * P_ELEMS * 2)      // 110592 B

__device__ __forceinline__ void load_panel(uint32_t sbuf,
                                           const bf16* __restrict__ Ah,
                                           const bf16* __restrict__ Al,
                                           const bf16* __restrict__ WTh,
                                           const bf16* __restrict__ WTl,
                                           int bm, int bn, int k0, int K, int tid) {
    #pragma unroll
    for (int u = 0; u < 4; ++u) {
        int i = tid + u * 256;
        int r = i >> 3, c8 = (i & 7) << 3;
        size_t src = (size_t)(bm + r) * K + k0 + c8;
        uint32_t doff = (uint32_t)((r * 72 + c8) * 2);
        cpasync16(sbuf + P_AH * 2 + doff, Ah + src);
        cpasync16(sbuf + P_AL * 2 + doff, Al + src);
    }
    #pragma unroll
    for (int u = 0; u < 2; ++u) {
        int i = tid + u * 256;
        int r = i >> 3, c8 = (i & 7) << 3;
        size_t src = (size_t)(bn + r) * K + k0 + c8;
        uint32_t doff = (uint32_t)((r * 72 + c8) * 2);
        cpasync16(sbuf + P_BH * 2 + doff, WTh + src);
        cpasync16(sbuf + P_BL * 2 + doff, WTl + src);
    }
}

__device__ __forceinline__ void tgemm_body(const bf16* __restrict__ Ah,
                                           const bf16* __restrict__ Al,
                                           const bf16* __restrict__ WTh,
                                           const bf16* __restrict__ WTl,
                                           float* __restrict__ C, int Nn, int K, int bn0) {
    extern __shared__ bf16 sm[];
    const uint32_t sbase = (uint32_t)__cvta_generic_to_shared(sm);
    const int bm = blockIdx.y * 128;
    const int bn = (blockIdx.x + bn0) * 64;
    const int tid = threadIdx.x;
    const int wid = tid >> 5, lane = tid & 31;
    const int wm = (wid >> 1) * 32;
    const int wn = (wid & 1) * 32;

    float acc[2][4][4];
    #pragma unroll
    for (int i = 0; i < 2; i++)
        #pragma unroll
        for (int j = 0; j < 4; j++)
            #pragma unroll
            for (int k = 0; k < 4; k++) acc[i][j][k] = 0.f;

    const int NP = K >> 6;
    load_panel(sbase, Ah, Al, WTh, WTl, bm, bn, 0, K, tid);
    CP_COMMIT();

    for (int p = 0; p < NP; ++p) {
        if (p + 1 < NP) {
            load_panel(sbase + ((p + 1) & 1) * P_ELEMS * 2,
                       Ah, Al, WTh, WTl, bm, bn, (p + 1) << 6, K, tid);
            CP_COMMIT();
            CP_WAIT(1);
        } else {
            CP_WAIT(0);
        }
        __syncthreads();

        const bf16* buf = sm + (p & 1) * P_ELEMS;
        const bf16* sAh = buf + P_AH;
        const bf16* sAl = buf + P_AL;
        const bf16* sBh = buf + P_BH;
        const bf16* sBl = buf + P_BL;

        #pragma unroll
        for (int ks = 0; ks < 4; ++ks) {
            const int c = ks * 16 + (lane & 3) * 2;
            const int ra = wm + (lane >> 2);
            uint32_t ah[2][4], al[2][4], bh[4][2], bl[4][2];
            #pragma unroll
            for (int mf = 0; mf < 2; ++mf) {
                lda(ah[mf], sAh, ra + mf * 16, c);
                lda(al[mf], sAl, ra + mf * 16, c);
            }
            #pragma unroll
            for (int nf = 0; nf < 4; ++nf) {
                ldb(bh[nf], sBh, wn + nf * 8 + (lane >> 2), c);
                ldb(bl[nf], sBl, wn + nf * 8 + (lane >> 2), c);
            }
            #pragma unroll
            for (int mf = 0; mf < 2; ++mf)
                #pragma unroll
                for (int nf = 0; nf < 4; ++nf) {
                    mma16816(acc[mf][nf], ah[mf], bh[nf]);
                    mma16816(acc[mf][nf], ah[mf], bl[nf]);
                    mma16816(acc[mf][nf], al[mf], bh[nf]);
                }
        }
        __syncthreads();
    }

    #pragma unroll
    for (int mf = 0; mf < 2; ++mf) {
        int row0 = bm + wm + mf * 16 + (lane >> 2);
        #pragma unroll
        for (int nf = 0; nf < 4; ++nf) {
            int col = bn + wn + nf * 8 + (lane & 3) * 2;
            if (col < Nn) {
                float* p0 = C + (size_t)row0 * Nn + col;
                float* p1 = C + (size_t)(row0 + 8) * Nn + col;
                p0[0] = acc[mf][nf][0];
                if (col + 1 < Nn) p0[1] = acc[mf][nf][1];
                p1[0] = acc[mf][nf][2];
                if (col + 1 < Nn) p1[1] = acc[mf][nf][3];
            }
        }
    }
}

__global__ void __launch_bounds__(256) k_tgemm_in(int bn0) {
    tgemm_body(g_xh, g_xl, g_WinTh, g_WinTl, g_zx, NPROJ, DD, bn0);
}
__global__ void __launch_bounds__(256) k_tgemm_out(float* __restrict__ out) {
    tgemm_body(g_yh, g_yl, g_WoutTh, g_WoutTl, out, DD, DIN, 0);
}

// ---------------- K1: LayerNorm + residual copy ----------------
__global__ void __launch_bounds__(256) k_ln(const float* __restrict__ hid,
                                            const float* __restrict__ w,
                                            const float* __restrict__ b,
                                            float* __restrict__ resid) {
    int row = blockIdx.x, t = threadIdx.x;
    float v = hid[row*DD + t];
    float s = v, q = v*v;
    #pragma unroll
    for (int o = 16; o; o >>= 1) {
        s += __shfl_xor_sync(0xffffffffu, s, o);
        q += __shfl_xor_sync(0xffffffffu, q, o);
    }
    __shared__ float r1[8], r2[8];
    if ((t & 31) == 0) { r1[t>>5] = s; r2[t>>5] = q; }
    __syncthreads();
    __shared__ float smu, srs;
    if (t == 0) {
        float S = 0.f, Qs = 0.f;
        for (int i = 0; i < 8; i++) { S += r1[i]; Qs += r2[i]; }
        float mu = S / 256.f;
        smu = mu;
        srs = rsqrtf(Qs/256.f - mu*mu + 1e-5f);
    }
    __syncthreads();
    float xv = (v - smu) * srs * w[t] + b[t];
    float hi = rtbf(xv);
    g_xh[row*DD + t] = __float2bfloat16(hi);
    g_xl[row*DD + t] = __float2bfloat16(xv - hi);
    resid[row*DD + t] = v;
}

// ---------------- K3: causal depthwise conv + SiLU, softplus(dt) ----------------
__global__ void __launch_bounds__(256) k_conv(const float* __restrict__ cw,
                                              const float* __restrict__ cb,
                                              const float* __restrict__ dtb,
                                              const float* __restrict__ Alog) {
    int idx = blockIdx.x * 256 + threadIdx.x;
    if (idx >= ROWS * 648) return;
    int c = idx % 648;
    int row = idx / 648;
    int b = row / LL, l = row % LL;
    if (c < CDIM) {
        float acc = cb[c];
        #pragma unroll
        for (int k = 0; k < 4; k++) {
            int ls = l + k - 3;
            if (ls >= 0) acc += cw[c*4 + k] * g_zx[(b*LL + ls)*NPROJ + 512 + c];
        }
        float sv = fsilu(acc);
        if (c < DIN) {
            g_xact[row*DIN + c] = sv;
        } else if (c < 576) {
            float hi = rtbf(sv);
            g_Bmh[row*NST + (c - 512)] = __float2bfloat16(hi);
            g_Bml[row*NST + (c - 512)] = __float2bfloat16(sv - hi);
        } else {
            float hi = rtbf(sv);
            g_Cmh[row*NST + (c - 576)] = __float2bfloat16(hi);
            g_Cml[row*NST + (c - 576)] = __float2bfloat16(sv - hi);
        }
    } else {
        int h = c - CDIM;
        float raw = g_zx[row*NPROJ + 1152 + h] + dtb[h];
        float dt = (raw > 20.f) ? raw : log1pf(__expf(raw));
        g_dt[row*NH + h]   = dt;
        g_dlog[row*NH + h] = -dt * __expf(Alog[h]);
    }
}

// ---- inclusive warp-scan of 64 values ----
__device__ __forceinline__ void scan64(float* sl, float* sw0tot, int tid, float v) {
    if (tid < 64) {
        #pragma unroll
        for (int o = 1; o < 32; o <<= 1) {
            float n = __shfl_up_sync(0xffffffffu, v, o);
            if ((tid & 31) >= o) v += n;
        }
        sl[tid] = v;
        if (tid == 31) *sw0tot = v;
    }
    __syncthreads();
    if (tid >= 32 && tid < 64) sl[tid] += *sw0tot;
    __syncthreads();
}

// ---------------- K4: per-chunk partial state via HMMA bf16x3 ----------------
__global__ void __launch_bounds__(256) k_cstate() {
    __shared__ bf16 sXh[64*72], sXl[64*72], sBTh[64*72], sBTl[64*72];
    __shared__ float sl[64], scoef[64], sw0;
    int bid = blockIdx.x;
    int c = bid & 31, h = (bid >> 5) & 7, b = bid >> 8;
    int tid = threadIdx.x;
    int t0 = b*LL + c*QC;

    float lv = (tid < 64) ? g_dlog[(t0 + tid)*NH + h] : 0.f;
    scan64(sl, &sw0, tid, lv);
    float lend = sl[63];
    if (tid < 64) scoef[tid] = __expf(lend - sl[tid]) * g_dt[(t0 + tid)*NH + h];
    if (tid == 0) g_lend[bid] = lend;
    __syncthreads();

    #pragma unroll
    for (int u = 0; u < 4; ++u) {
        int i = tid + u * 256;
        int j = i >> 4, n4 = (i & 15) << 2;
        float cf = scoef[j];
        float4 vx = *(const float4*)(g_xact + (size_t)(t0 + j)*DIN + h*64 + n4);
        vx.x *= cf; vx.y *= cf; vx.z *= cf; vx.w *= cf;
        store4T(sXh, sXl, n4, j, vx);
        uint2 bh2 = *(const uint2*)(g_Bmh + (size_t)(t0 + j)*NST + n4);
        uint2 bl2 = *(const uint2*)(g_Bml + (size_t)(t0 + j)*NST + n4);
        const bf16* ph = (const bf16*)&bh2;
        const bf16* pl = (const bf16*)&bl2;
        #pragma unroll
        for (int k = 0; k < 4; k++) {
            sBTh[(n4 + k)*72 + j] = ph[k];
            sBTl[(n4 + k)*72 + j] = pl[k];
        }
    }
    __syncthreads();

    const int wid = tid >> 5, lane = tid & 31;
    const int wm = (wid >> 1) * 16, wn = (wid & 1) * 32;
    const int r0 = wm + (lane >> 2);
    float acc[4][4];
    #pragma unroll
    for (int i = 0; i < 4; i++)
        #pragma unroll
        for (int j = 0; j < 4; j++) acc[i][j] = 0.f;

    #pragma unroll
    for (int ks = 0; ks < 4; ++ks) {
        const int cc = ks * 16 + (lane & 3) * 2;
        uint32_t ah[4], al[4], bh[4][2], bl[4][2];
        lda(ah, sXh, r0, cc);
        lda(al, sXl, r0, cc);
        #pragma unroll
        for (int nf = 0; nf < 4; ++nf) {
            ldb(bh[nf], sBTh, wn + nf * 8 + (lane >> 2), cc);
            ldb(bl[nf], sBTl, wn + nf * 8 + (lane >> 2), cc);
        }
        #pragma unroll
        for (int nf = 0; nf < 4; ++nf) {
            mma16816(acc[nf], ah, bh[nf]);
            mma16816(acc[nf], ah, bl[nf]);
            mma16816(acc[nf], al, bh[nf]);
        }
    }

    float* op = g_chunkS + (size_t)bid * 4096;
    #pragma unroll
    for (int nf = 0; nf < 4; ++nf) {
        int n0 = wn + nf * 8 + (lane & 3) * 2;
        op[r0*64 + n0]     = acc[nf][0]; op[r0*64 + n0 + 1]     = acc[nf][1];
        op[(r0+8)*64 + n0] = acc[nf][2]; op[(r0+8)*64 + n0 + 1] = acc[nf][3];
    }
}

// ---------------- K5: inter-chunk recurrence, batched prefetch (MLP 8) ----------------
__global__ void __launch_bounds__(256) k_seq() {
    __shared__ float sa[NC];
    int bh = blockIdx.x >> 2, part = blockIdx.x & 3, tid = threadIdx.x;
    if (tid < NC) sa[tid] = __expf(g_lend[bh*NC + tid]);
    __syncthreads();
    int e = (part * 256 + tid) * 4;
    size_t base0 = (size_t)bh * NC * 4096 + e;
    float4 s = make_float4(0.f, 0.f, 0.f, 0.f);
    for (int cb = 0; cb < NC; cb += 8) {
        float4 v[8];
        #pragma unroll
        for (int k = 0; k < 8; k++)
            v[k] = *(const float4*)(g_chunkS + base0 + (size_t)(cb + k) * 4096);
        #pragma unroll
        for (int k = 0; k < 8; k++) {
            size_t off = base0 + (size_t)(cb + k) * 4096;
            float h0 = rtbf(s.x), h1 = rtbf(s.y), h2 = rtbf(s.z), h3 = rtbf(s.w);
            *(uint2*)(g_Sinh + off) = make_uint2(pk(h0, h1), pk(h2, h3));
            *(uint2*)(g_Sinl + off) = make_uint2(pk(s.x - h0, s.y - h1), pk(s.z - h2, s.w - h3));
            float a = sa[cb + k];
            s.x = s.x*a + v[k].x; s.y = s.y*a + v[k].y;
            s.z = s.z*a + v[k].z; s.w = s.w*a + v[k].w;
        }
    }
}

// ---------------- K6: intra-chunk Y via HMMA bf16x3 (D folded into M diag) ----------------
__global__ void __launch_bounds__(256) k_y(const float* __restrict__ Dp) {
    extern __shared__ bf16 sy[];
    bf16* sBh = sy;
    bf16* sBl = sy + 4608;
    bf16* sCh = sy + 2*4608;
    bf16* sCl = sy + 3*4608;
    bf16* sSh = sy + 4*4608;
    bf16* sSl = sy + 5*4608;
    __shared__ float sl[64], sdt[64], sw0;

    int bid = blockIdx.x;
    int c = bid & 31, h = (bid >> 5) & 7, b = bid >> 8;
    int tid = threadIdx.x;
    int t0 = b*LL + c*QC;
    float Dh = Dp[h];

    float lv = (tid < 64) ? g_dlog[(t0 + tid)*NH + h] : 0.f;
    if (tid < 64) sdt[tid] = g_dt[(t0 + tid)*NH + h];
    scan64(sl, &sw0, tid, lv);

    #pragma unroll
    for (int u = 0; u < 2; ++u) {
        int i = tid + u * 256;
        int r = i >> 3, c8 = (i & 7) << 3;
        size_t gs = (size_t)(t0 + r)*NST + c8;
        *(uint4*)(sBh + r*72 + c8) = *(const uint4*)(g_Bmh + gs);
        *(uint4*)(sBl + r*72 + c8) = *(const uint4*)(g_Bml + gs);
        *(uint4*)(sCh + r*72 + c8) = *(const uint4*)(g_Cmh + gs);
        *(uint4*)(sCl + r*72 + c8) = *(const uint4*)(g_Cml + gs);
        size_t ss = (size_t)bid*4096 + r*64 + c8;
        *(uint4*)(sSh + r*72 + c8) = *(const uint4*)(g_Sinh + ss);
        *(uint4*)(sSl + r*72 + c8) = *(const uint4*)(g_Sinl + ss);
    }
    __syncthreads();

    const int wid = tid >> 5, lane = tid & 31;
    const int wm = (wid >> 1) * 16, wn = (wid & 1) * 32;
    const int r0 = wm + (lane >> 2);

    float g[4][4], g3[4][4];
    #pragma unroll
    for (int i = 0; i < 4; i++)
        #pragma unroll
        for (int j = 0; j < 4; j++) { g[i][j] = 0.f; g3[i][j] = 0.f; }

    #pragma unroll
    for (int ks = 0; ks < 4; ++ks) {
        const int cc = ks * 16 + (lane & 3) * 2;
        uint32_t ah[4], al[4], bh[2], bl[2];
        lda(ah, sCh, r0, cc);
        lda(al, sCl, r0, cc);
        #pragma unroll
        for (int nf = 0; nf < 4; ++nf) {
            int nr = wn + nf * 8 + (lane >> 2);
            ldb(bh, sBh, nr, cc);  ldb(bl, sBl, nr, cc);
            mma16816(g[nf], ah, bh);
            mma16816(g[nf], ah, bl);
            mma16816(g[nf], al, bh);
            ldb(bh, sSh, nr, cc);  ldb(bl, sSl, nr, cc);
            mma16816(g3[nf], ah, bh);
            mma16816(g3[nf], ah, bl);
            mma16816(g3[nf], al, bh);
        }
    }
    __syncthreads();   // reuse sB for M, sS for X^T

    float Lr0 = sl[r0], Lr8 = sl[r0 + 8];
    #pragma unroll
    for (int nf = 0; nf < 4; ++nf) {
        int jn = wn + nf * 8 + (lane & 3) * 2;
        #pragma unroll
        for (int jj = 0; jj < 2; ++jj) {
            int j = jn + jj;
            float Lj = sl[j], dtj = sdt[j];
            float m0 = (r0     >= j) ? __expf(Lr0 - Lj) * dtj * g[nf][jj]     : 0.f;
            float m8 = (r0 + 8 >= j) ? __expf(Lr8 - Lj) * dtj * g[nf][2 + jj] : 0.f;
            if (r0 == j)     m0 += Dh;
            if (r0 + 8 == j) m8 += Dh;
            float h0 = rtbf(m0), h8 = rtbf(m8);
            sBh[r0*72 + j]     = __float2bfloat16(h0);
            sBl[r0*72 + j]     = __float2bfloat16(m0 - h0);
            sBh[(r0+8)*72 + j] = __float2bfloat16(h8);
            sBl[(r0+8)*72 + j] = __float2bfloat16(m8 - h8);
        }
    }
    #pragma unroll
    for (int u = 0; u < 4; ++u) {
        int i = tid + u * 256;
        int j = i >> 4, p4 = (i & 15) << 2;
        float4 vx = *(const float4*)(g_xact + (size_t)(t0 + j)*DIN + h*64 + p4);
        store4T(sSh, sSl, p4, j, vx);
    }
    __syncthreads();

    float Y[4][4];
    #pragma unroll
    for (int i = 0; i < 4; i++)
        #pragma unroll
        for (int j = 0; j < 4; j++) Y[i][j] = 0.f;
    #pragma unroll
    for (int ks = 0; ks < 4; ++ks) {
        const int cc = ks * 16 + (lane & 3) * 2;
        uint32_t ah[4], al[4], bh[2], bl[2];
        lda(ah, sBh, r0, cc);
        lda(al, sBl, r0, cc);
        #pragma unroll
        for (int nf = 0; nf < 4; ++nf) {
            int nr = wn + nf * 8 + (lane >> 2);
            ldb(bh, sSh, nr, cc);  ldb(bl, sSl, nr, cc);
            mma16816(Y[nf], ah, bh);
            mma16816(Y[nf], ah, bl);
            mma16816(Y[nf], al, bh);
        }
    }

    float e0 = __expf(Lr0), e8 = __expf(Lr8);
    #pragma unroll
    for (int nf = 0; nf < 4; ++nf) {
        int p0 = wn + nf * 8 + (lane & 3) * 2;
        #pragma unroll
        for (int jj = 0; jj < 2; ++jj) {
            int p = p0 + jj;
            float y0 = Y[nf][jj]     + e0 * g3[nf][jj];
            float y8 = Y[nf][2 + jj] + e8 * g3[nf][2 + jj];
            g_y[(size_t)(t0 + r0)*DIN     + h*64 + p] = y0;
            g_y[(size_t)(t0 + r0 + 8)*DIN + h*64 + p] = y8;
        }
    }
}
#define KY_DSMEM (6*4608*2)

// ---------------- K7: gating + RMSNorm; emits bf16 hi/lo ----------------
__global__ void __launch_bounds__(256) k_gate(const float* __restrict__ rmsw) {
    int row = blockIdx.x, t = threadIdx.x;
    float gv[2]; float ss = 0.f;
    #pragma unroll
    for (int k = 0; k < 2; k++) {
        int i = t + k*256;
        float z = g_zx[row*NPROJ + i];
        float v = g_y[row*DIN + i] * fsilu(z);
        gv[k] = v; ss += v*v;
    }
    #pragma unroll
    for (int o = 16; o; o >>= 1) ss += __shfl_xor_sync(0xffffffffu, ss, o);
    __shared__ float red[8];
    if ((t & 31) == 0) red[t>>5] = ss;
    __syncthreads();
    __shared__ float scale;
    if (t == 0) {
        float tot = 0.f;
        for (int i = 0; i < 8; i++) tot += red[i];
        scale = rsqrtf(tot/512.f + 1e-5f);
    }
    __syncthreads();
    #pragma unroll
    for (int k = 0; k < 2; k++) {
        int i = t + k*256;
        float v = gv[k] * scale * rmsw[i];
        float hi = rtbf(v);
        g_yh[row*DIN + i] = __float2bfloat16(hi);
        g_yl[row*DIN + i] = __float2bfloat16(v - hi);
    }
}

// ---------------- launch ----------------
extern "C" void kernel_launch(void* const* d_in, const int* in_sizes, int n_in,
                              void* d_out, int out_size) {
    const float* hid   = (const float*)d_in[0];
    const float* normw = (const float*)d_in[1];
    const float* normb = (const float*)d_in[2];
    const float* Win   = (const float*)d_in[3];
    const float* convw = (const float*)d_in[4];
    const float* convb = (const float*)d_in[5];
    const float* dtb   = (const float*)d_in[6];
    const float* Alog  = (const float*)d_in[7];
    const float* Dp    = (const float*)d_in[8];
    const float* rmsw  = (const float*)d_in[9];
    const float* Wout  = (const float*)d_in[10];
    float* out   = (float*)d_out;
    float* resid = out + out_size/2;

    bf16 *winTh, *winTl, *woutTh, *woutTl;
    cudaGetSymbolAddress((void**)&winTh,  g_WinTh);
    cudaGetSymbolAddress((void**)&winTl,  g_WinTl);
    cudaGetSymbolAddress((void**)&woutTh, g_WoutTh);
    cudaGetSymbolAddress((void**)&woutTl, g_WoutTl);

    static cudaStream_t s_side = nullptr;
    static cudaEvent_t ev_fork = nullptr, ev_join = nullptr;
    if (!s_side) {
        cudaStreamCreateWithFlags(&s_side, cudaStreamNonBlocking);
        cudaEventCreateWithFlags(&ev_fork, cudaEventDisableTiming);
        cudaEventCreateWithFlags(&ev_join, cudaEventDisableTiming);
    }

    cudaFuncSetAttribute(k_tgemm_in,  cudaFuncAttributeMaxDynamicSharedMemorySize, TG_DSMEM);
    cudaFuncSetAttribute(k_tgemm_out, cudaFuncAttributeMaxDynamicSharedMemorySize, TG_DSMEM);
    cudaFuncSetAttribute(k_y,         cudaFuncAttributeMaxDynamicSharedMemorySize, KY_DSMEM);

    k_prep <<<dim3(1280/32, DD/32), dim3(32, 8)>>>(Win, winTh, winTl, DD, NPROJ, 1280);
    k_prep <<<dim3(DD/32, DIN/32),  dim3(32, 8)>>>(Wout, woutTh, woutTl, DIN, DD, DD);
    k_ln   <<<ROWS, 256>>>(hid, normw, normb, resid);

    // fork: z-column GEMM (n-blocks 0..7) runs on side stream, overlapped with scan chain
    cudaEventRecord(ev_fork, 0);
    cudaStreamWaitEvent(s_side, ev_fork, 0);
    k_tgemm_in <<<dim3(8, ROWS/128), 256, TG_DSMEM, s_side>>>(0);
    cudaEventRecord(ev_join, s_side);

    // main stream: xBC+dt GEMM (n-blocks 8..18), then the scan chain
    k_tgemm_in <<<dim3(11, ROWS/128), 256, TG_DSMEM>>>(8);
    k_conv     <<<(ROWS*648 + 255)/256, 256>>>(convw, convb, dtb, Alog);
    k_cstate   <<<BB*NH*NC, 256>>>();
    k_seq      <<<BB*NH*4, 256>>>();
    k_y        <<<BB*NH*NC, 256, KY_DSMEM>>>(Dp);

    // join: gate needs z columns
    cudaStreamWaitEvent(0, ev_join, 0);
    k_gate     <<<ROWS, 256>>>(rmsw);
    k_tgemm_out<<<dim3(DD/64, ROWS/128), 256, TG_DSMEM>>>(out);
}

// round 14
// speedup vs baseline: 1.4548x; 1.4548x over previous
#include <cuda_runtime.h>
#include <cuda_bf16.h>
#include <math.h>
#include <stdint.h>

// ---------------- problem constants ----------------
#define BB    2
#define LL    2048
#define DD    256
#define DIN   512
#define NH    8
#define NST   64
#define CDIM  640
#define NPROJ 1160
#define ROWS  (BB*LL)      // 4096
#define NC    32           // chunks per sequence
#define QC    64           // chunk length

typedef __nv_bfloat16 bf16;

// ---------------- scratch ----------------
__device__ __align__(16) bf16  g_xh    [ROWS*DD];
__device__ __align__(16) bf16  g_xl    [ROWS*DD];
__device__ __align__(16) float g_zx    [ROWS*NPROJ];
__device__ __align__(16) float g_xact  [ROWS*DIN];
__device__ __align__(16) bf16  g_Bmh   [ROWS*NST];
__device__ __align__(16) bf16  g_Bml   [ROWS*NST];
__device__ __align__(16) bf16  g_Cmh   [ROWS*NST];
__device__ __align__(16) bf16  g_Cml   [ROWS*NST];
__device__ __align__(16) float g_dt    [ROWS*NH];
__device__ __align__(16) float g_dlog  [ROWS*NH];
__device__ __align__(16) float g_chunkS[BB*NH*NC*QC*NST];
__device__ __align__(16) float g_lend  [BB*NH*NC];
__device__ __align__(16) bf16  g_Sinh  [BB*NH*NC*QC*NST];
__device__ __align__(16) bf16  g_Sinl  [BB*NH*NC*QC*NST];
__device__ __align__(16) float g_y     [ROWS*DIN];
__device__ __align__(16) bf16  g_yh    [ROWS*DIN];
__device__ __align__(16) bf16  g_yl    [ROWS*DIN];
__device__ __align__(16) bf16  g_WinTh [1280*DD];           // [n][k], N padded
__device__ __align__(16) bf16  g_WinTl [1280*DD];
__device__ __align__(16) bf16  g_WoutTh[DD*DIN];
__device__ __align__(16) bf16  g_WoutTl[DD*DIN];

__device__ __forceinline__ float fsilu(float x) {
    return __fdividef(x, 1.f + __expf(-x));
}

// ================= warp MMA helpers =================
__device__ __forceinline__ void mma16816(float* c, const uint32_t* a, const uint32_t* b) {
    asm volatile(
        "mma.sync.aligned.m16n8k16.row.col.f32.bf16.bf16.f32 "
        "{%0,%1,%2,%3}, {%4,%5,%6,%7}, {%8,%9}, {%0,%1,%2,%3};"
        : "+f"(c[0]), "+f"(c[1]), "+f"(c[2]), "+f"(c[3])
        : "r"(a[0]), "r"(a[1]), "r"(a[2]), "r"(a[3]), "r"(b[0]), "r"(b[1]));
}
__device__ __forceinline__ uint32_t pk(float a, float b) {
    __nv_bfloat162 t = __floats2bfloat162_rn(a, b);
    return *reinterpret_cast<uint32_t*>(&t);
}
__device__ __forceinline__ float rtbf(float v) {
    return __bfloat162float(__float2bfloat16(v));
}
__device__ __forceinline__ void store4T(bf16* sh, bf16* slo, int q4, int j, float4 v) {
    float f[4] = {v.x, v.y, v.z, v.w};
    #pragma unroll
    for (int k = 0; k < 4; k++) {
        float hi = rtbf(f[k]);
        sh [(q4 + k) * 72 + j] = __float2bfloat16(hi);
        slo[(q4 + k) * 72 + j] = __float2bfloat16(f[k] - hi);
    }
}
__device__ __forceinline__ void lda(uint32_t* a, const bf16* s, int r0, int c) {
    int o0 = r0 * 72 + c, o8 = o0 + 8 * 72;
    a[0] = *(const uint32_t*)(s + o0);
    a[1] = *(const uint32_t*)(s + o8);
    a[2] = *(const uint32_t*)(s + o0 + 8);
    a[3] = *(const uint32_t*)(s + o8 + 8);
}
__device__ __forceinline__ void ldb(uint32_t* b, const bf16* s, int n, int c) {
    int o = n * 72 + c;
    b[0] = *(const uint32_t*)(s + o);
    b[1] = *(const uint32_t*)(s + o + 8);
}
__device__ __forceinline__ void cpasync16(uint32_t saddr, const void* g) {
    asm volatile("cp.async.cg.shared.global [%0], [%1], 16;" :: "r"(saddr), "l"(g));
}
#define CP_COMMIT()  asm volatile("cp.async.commit_group;")
#define CP_WAIT(n)   asm volatile("cp.async.wait_group %0;" :: "n"(n))

// ---------------- K0: transpose + hi/lo split of weights ----------------
__global__ void k_prep(const float* __restrict__ W, bf16* __restrict__ Th,
                       bf16* __restrict__ Tl, int K, int N, int Npad) {
    __shared__ float t[32][33];
    int n0 = blockIdx.x * 32, k0 = blockIdx.y * 32;
    int tx = threadIdx.x, ty = threadIdx.y;
    #pragma unroll
    for (int i = 0; i < 4; i++) {
        int k = k0 + ty + i * 8;
        t[ty + i * 8][tx] = (n0 + tx < N) ? W[(size_t)k * N + n0 + tx] : 0.f;
    }
    __syncthreads();
    #pragma unroll
    for (int i = 0; i < 4; i++) {
        int n = n0 + ty + i * 8;
        if (n < Npad) {
            float v = t[tx][ty + i * 8];
            float hi = rtbf(v);
            Th[(size_t)n * K + k0 + tx] = __float2bfloat16(hi);
            Tl[(size_t)n * K + k0 + tx] = __float2bfloat16(v - hi);
        }
    }
}

// ======== pipelined GEMM (r7 config: K-panel 64, stride 72) ========
#define P_AH 0
#define P_AL (128*72)
#define P_BH (2*128*72)
#define P_BL (2*128*72 + 64*72)
#define P_ELEMS (2*128*72 + 2*64*72)
#define TG_DSMEM (2 * P_ELEMS * 2)      // 110592 B

__device__ __forceinline__ void load_panel(uint32_t sbuf,
                                           const bf16* __restrict__ Ah,
                                           const bf16* __restrict__ Al,
                                           const bf16* __restrict__ WTh,
                                           const bf16* __restrict__ WTl,
                                           int bm, int bn, int k0, int K, int tid) {
    #pragma unroll
    for (int u = 0; u < 4; ++u) {
        int i = tid + u * 256;
        int r = i >> 3, c8 = (i & 7) << 3;
        size_t src = (size_t)(bm + r) * K + k0 + c8;
        uint32_t doff = (uint32_t)((r * 72 + c8) * 2);
        cpasync16(sbuf + P_AH * 2 + doff, Ah + src);
        cpasync16(sbuf + P_AL * 2 + doff, Al + src);
    }
    #pragma unroll
    for (int u = 0; u < 2; ++u) {
        int i = tid + u * 256;
        int r = i >> 3, c8 = (i & 7) << 3;
        size_t src = (size_t)(bn + r) * K + k0 + c8;
        uint32_t doff = (uint32_t)((r * 72 + c8) * 2);
        cpasync16(sbuf + P_BH * 2 + doff, WTh + src);
        cpasync16(sbuf + P_BL * 2 + doff, WTl + src);
    }
}

__device__ __forceinline__ void tgemm_body(const bf16* __restrict__ Ah,
                                           const bf16* __restrict__ Al,
                                           const bf16* __restrict__ WTh,
                                           const bf16* __restrict__ WTl,
                                           float* __restrict__ C, int Nn, int K) {
    extern __shared__ bf16 sm[];
    const uint32_t sbase = (uint32_t)__cvta_generic_to_shared(sm);
    const int bm = blockIdx.y * 128;
    const int bn = blockIdx.x * 64;
    const int tid = threadIdx.x;
    const int wid = tid >> 5, lane = tid & 31;
    const int wm = (wid >> 1) * 32;
    const int wn = (wid & 1) * 32;

    float acc[2][4][4];
    #pragma unroll
    for (int i = 0; i < 2; i++)
        #pragma unroll
        for (int j = 0; j < 4; j++)
            #pragma unroll
            for (int k = 0; k < 4; k++) acc[i][j][k] = 0.f;

    const int NP = K >> 6;
    load_panel(sbase, Ah, Al, WTh, WTl, bm, bn, 0, K, tid);
    CP_COMMIT();

    for (int p = 0; p < NP; ++p) {
        if (p + 1 < NP) {
            load_panel(sbase + ((p + 1) & 1) * P_ELEMS * 2,
                       Ah, Al, WTh, WTl, bm, bn, (p + 1) << 6, K, tid);
            CP_COMMIT();
            CP_WAIT(1);
        } else {
            CP_WAIT(0);
        }
        __syncthreads();

        const bf16* buf = sm + (p & 1) * P_ELEMS;
        const bf16* sAh = buf + P_AH;
        const bf16* sAl = buf + P_AL;
        const bf16* sBh = buf + P_BH;
        const bf16* sBl = buf + P_BL;

        #pragma unroll
        for (int ks = 0; ks < 4; ++ks) {
            const int c = ks * 16 + (lane & 3) * 2;
            const int ra = wm + (lane >> 2);
            uint32_t ah[2][4], al[2][4], bh[4][2], bl[4][2];
            #pragma unroll
            for (int mf = 0; mf < 2; ++mf) {
                lda(ah[mf], sAh, ra + mf * 16, c);
                lda(al[mf], sAl, ra + mf * 16, c);
            }
            #pragma unroll
            for (int nf = 0; nf < 4; ++nf) {
                ldb(bh[nf], sBh, wn + nf * 8 + (lane >> 2), c);
                ldb(bl[nf], sBl, wn + nf * 8 + (lane >> 2), c);
            }
            #pragma unroll
            for (int mf = 0; mf < 2; ++mf)
                #pragma unroll
                for (int nf = 0; nf < 4; ++nf) {
                    mma16816(acc[mf][nf], ah[mf], bh[nf]);
                    mma16816(acc[mf][nf], ah[mf], bl[nf]);
                    mma16816(acc[mf][nf], al[mf], bh[nf]);
                }
        }
        __syncthreads();
    }

    #pragma unroll
    for (int mf = 0; mf < 2; ++mf) {
        int row0 = bm + wm + mf * 16 + (lane >> 2);
        #pragma unroll
        for (int nf = 0; nf < 4; ++nf) {
            int col = bn + wn + nf * 8 + (lane & 3) * 2;
            if (col < Nn) {
                float* p0 = C + (size_t)row0 * Nn + col;
                float* p1 = C + (size_t)(row0 + 8) * Nn + col;
                p0[0] = acc[mf][nf][0];
                if (col + 1 < Nn) p0[1] = acc[mf][nf][1];
                p1[0] = acc[mf][nf][2];
                if (col + 1 < Nn) p1[1] = acc[mf][nf][3];
            }
        }
    }
}

__global__ void __launch_bounds__(256) k_tgemm_in() {
    tgemm_body(g_xh, g_xl, g_WinTh, g_WinTl, g_zx, NPROJ, DD);
}
__global__ void __launch_bounds__(256) k_tgemm_out(float* __restrict__ out) {
    tgemm_body(g_yh, g_yl, g_WoutTh, g_WoutTl, out, DD, DIN);
}

// ---------------- K1: LayerNorm + residual copy ----------------
__global__ void __launch_bounds__(256) k_ln(const float* __restrict__ hid,
                                            const float* __restrict__ w,
                                            const float* __restrict__ b,
                                            float* __restrict__ resid) {
    int row = blockIdx.x, t = threadIdx.x;
    float v = hid[row*DD + t];
    float s = v, q = v*v;
    #pragma unroll
    for (int o = 16; o; o >>= 1) {
        s += __shfl_xor_sync(0xffffffffu, s, o);
        q += __shfl_xor_sync(0xffffffffu, q, o);
    }
    __shared__ float r1[8], r2[8];
    if ((t & 31) == 0) { r1[t>>5] = s; r2[t>>5] = q; }
    __syncthreads();
    __shared__ float smu, srs;
    if (t == 0) {
        float S = 0.f, Qs = 0.f;
        for (int i = 0; i < 8; i++) { S += r1[i]; Qs += r2[i]; }
        float mu = S / 256.f;
        smu = mu;
        srs = rsqrtf(Qs/256.f - mu*mu + 1e-5f);
    }
    __syncthreads();
    float xv = (v - smu) * srs * w[t] + b[t];
    float hi = rtbf(xv);
    g_xh[row*DD + t] = __float2bfloat16(hi);
    g_xl[row*DD + t] = __float2bfloat16(xv - hi);
    resid[row*DD + t] = v;
}

// ---------------- K3a: conv, register sliding window (reads each input once) ----------
// grid (CDIM/128, LL/64, BB); block 256 = [128 c][2 l-halves]; 32 L-steps per thread
__global__ void __launch_bounds__(256) k_conv(const float* __restrict__ cw,
                                              const float* __restrict__ cb) {
    int c = blockIdx.x * 128 + (threadIdx.x & 127);
    int lh = threadIdx.x >> 7;
    int b = blockIdx.z;
    int l0 = blockIdx.y * 64 + lh * 32;
    const float* zp = g_zx + (size_t)b * LL * NPROJ + 512 + c;
    float cw0 = cw[c*4], cw1 = cw[c*4+1], cw2 = cw[c*4+2], cw3 = cw[c*4+3];
    float bias = cb[c];
    float w0 = (l0 >= 3) ? zp[(size_t)(l0-3) * NPROJ] : 0.f;
    float w1 = (l0 >= 2) ? zp[(size_t)(l0-2) * NPROJ] : 0.f;
    float w2 = (l0 >= 1) ? zp[(size_t)(l0-1) * NPROJ] : 0.f;
    int row = b * LL + l0;
    if (c < DIN) {
        float* xp = g_xact + (size_t)row * DIN + c;
        #pragma unroll 4
        for (int i = 0; i < 32; ++i) {
            float w3 = zp[(size_t)(l0 + i) * NPROJ];
            float sv = fsilu(bias + cw0*w0 + cw1*w1 + cw2*w2 + cw3*w3);
            xp[(size_t)i * DIN] = sv;
            w0 = w1; w1 = w2; w2 = w3;
        }
    } else if (c < DIN + NST) {
        int cc = c - DIN;
        bf16* ph = g_Bmh + (size_t)row * NST + cc;
        bf16* pl = g_Bml + (size_t)row * NST + cc;
        #pragma unroll 4
        for (int i = 0; i < 32; ++i) {
            float w3 = zp[(size_t)(l0 + i) * NPROJ];
            float sv = fsilu(bias + cw0*w0 + cw1*w1 + cw2*w2 + cw3*w3);
            float hi = rtbf(sv);
            ph[(size_t)i * NST] = __float2bfloat16(hi);
            pl[(size_t)i * NST] = __float2bfloat16(sv - hi);
            w0 = w1; w1 = w2; w2 = w3;
        }
    } else {
        int cc = c - DIN - NST;
        bf16* ph = g_Cmh + (size_t)row * NST + cc;
        bf16* pl = g_Cml + (size_t)row * NST + cc;
        #pragma unroll 4
        for (int i = 0; i < 32; ++i) {
            float w3 = zp[(size_t)(l0 + i) * NPROJ];
            float sv = fsilu(bias + cw0*w0 + cw1*w1 + cw2*w2 + cw3*w3);
            float hi = rtbf(sv);
            ph[(size_t)i * NST] = __float2bfloat16(hi);
            pl[(size_t)i * NST] = __float2bfloat16(sv - hi);
            w0 = w1; w1 = w2; w2 = w3;
        }
    }
}

// ---------------- K3b: softplus(dt) ----------------
__global__ void __launch_bounds__(256) k_dt(const float* __restrict__ dtb,
                                            const float* __restrict__ Alog) {
    int idx = blockIdx.x * 256 + threadIdx.x;    // ROWS*NH
    int row = idx >> 3, h = idx & 7;
    float raw = g_zx[(size_t)row * NPROJ + 1152 + h] + dtb[h];
    float dt = (raw > 20.f) ? raw : log1pf(__expf(raw));
    g_dt[idx]   = dt;
    g_dlog[idx] = -dt * __expf(Alog[h]);
}

// ---- inclusive warp-scan of 64 values ----
__device__ __forceinline__ void scan64(float* sl, float* sw0tot, int tid, float v) {
    if (tid < 64) {
        #pragma unroll
        for (int o = 1; o < 32; o <<= 1) {
            float n = __shfl_up_sync(0xffffffffu, v, o);
            if ((tid & 31) >= o) v += n;
        }
        sl[tid] = v;
        if (tid == 31) *sw0tot = v;
    }
    __syncthreads();
    if (tid >= 32 && tid < 64) sl[tid] += *sw0tot;
    __syncthreads();
}

// ---------------- K4: per-chunk partial state via HMMA bf16x3 ----------------
__global__ void __launch_bounds__(256) k_cstate() {
    __shared__ bf16 sXh[64*72], sXl[64*72], sBTh[64*72], sBTl[64*72];
    __shared__ float sl[64], scoef[64], sw0;
    int bid = blockIdx.x;
    int c = bid & 31, h = (bid >> 5) & 7, b = bid >> 8;
    int tid = threadIdx.x;
    int t0 = b*LL + c*QC;

    float lv = (tid < 64) ? g_dlog[(t0 + tid)*NH + h] : 0.f;
    scan64(sl, &sw0, tid, lv);
    float lend = sl[63];
    if (tid < 64) scoef[tid] = __expf(lend - sl[tid]) * g_dt[(t0 + tid)*NH + h];
    if (tid == 0) g_lend[bid] = lend;
    __syncthreads();

    #pragma unroll
    for (int u = 0; u < 4; ++u) {
        int i = tid + u * 256;
        int j = i >> 4, n4 = (i & 15) << 2;
        float cf = scoef[j];
        float4 vx = *(const float4*)(g_xact + (size_t)(t0 + j)*DIN + h*64 + n4);
        vx.x *= cf; vx.y *= cf; vx.z *= cf; vx.w *= cf;
        store4T(sXh, sXl, n4, j, vx);
        uint2 bh2 = *(const uint2*)(g_Bmh + (size_t)(t0 + j)*NST + n4);
        uint2 bl2 = *(const uint2*)(g_Bml + (size_t)(t0 + j)*NST + n4);
        const bf16* ph = (const bf16*)&bh2;
        const bf16* pl = (const bf16*)&bl2;
        #pragma unroll
        for (int k = 0; k < 4; k++) {
            sBTh[(n4 + k)*72 + j] = ph[k];
            sBTl[(n4 + k)*72 + j] = pl[k];
        }
    }
    __syncthreads();

    const int wid = tid >> 5, lane = tid & 31;
    const int wm = (wid >> 1) * 16, wn = (wid & 1) * 32;
    const int r0 = wm + (lane >> 2);
    float acc[4][4];
    #pragma unroll
    for (int i = 0; i < 4; i++)
        #pragma unroll
        for (int j = 0; j < 4; j++) acc[i][j] = 0.f;

    #pragma unroll
    for (int ks = 0; ks < 4; ++ks) {
        const int cc = ks * 16 + (lane & 3) * 2;
        uint32_t ah[4], al[4], bh[4][2], bl[4][2];
        lda(ah, sXh, r0, cc);
        lda(al, sXl, r0, cc);
        #pragma unroll
        for (int nf = 0; nf < 4; ++nf) {
            ldb(bh[nf], sBTh, wn + nf * 8 + (lane >> 2), cc);
            ldb(bl[nf], sBTl, wn + nf * 8 + (lane >> 2), cc);
        }
        #pragma unroll
        for (int nf = 0; nf < 4; ++nf) {
            mma16816(acc[nf], ah, bh[nf]);
            mma16816(acc[nf], ah, bl[nf]);
            mma16816(acc[nf], al, bh[nf]);
        }
    }

    float* op = g_chunkS + (size_t)bid * 4096;
    #pragma unroll
    for (int nf = 0; nf < 4; ++nf) {
        int n0 = wn + nf * 8 + (lane & 3) * 2;
        op[r0*64 + n0]     = acc[nf][0]; op[r0*64 + n0 + 1]     = acc[nf][1];
        op[(r0+8)*64 + n0] = acc[nf][2]; op[(r0+8)*64 + n0 + 1] = acc[nf][3];
    }
}

// ---------------- K5: inter-chunk recurrence, batched prefetch (MLP 8) ----------------
__global__ void __launch_bounds__(256) k_seq() {
    __shared__ float sa[NC];
    int bh = blockIdx.x >> 2, part = blockIdx.x & 3, tid = threadIdx.x;
    if (tid < NC) sa[tid] = __expf(g_lend[bh*NC + tid]);
    __syncthreads();
    int e = (part * 256 + tid) * 4;
    size_t base0 = (size_t)bh * NC * 4096 + e;
    float4 s = make_float4(0.f, 0.f, 0.f, 0.f);
    for (int cb = 0; cb < NC; cb += 8) {
        float4 v[8];
        #pragma unroll
        for (int k = 0; k < 8; k++)
            v[k] = *(const float4*)(g_chunkS + base0 + (size_t)(cb + k) * 4096);
        #pragma unroll
        for (int k = 0; k < 8; k++) {
            size_t off = base0 + (size_t)(cb + k) * 4096;
            float h0 = rtbf(s.x), h1 = rtbf(s.y), h2 = rtbf(s.z), h3 = rtbf(s.w);
            *(uint2*)(g_Sinh + off) = make_uint2(pk(h0, h1), pk(h2, h3));
            *(uint2*)(g_Sinl + off) = make_uint2(pk(s.x - h0, s.y - h1), pk(s.z - h2, s.w - h3));
            float a = sa[cb + k];
            s.x = s.x*a + v[k].x; s.y = s.y*a + v[k].y;
            s.z = s.z*a + v[k].z; s.w = s.w*a + v[k].w;
        }
    }
}

// ---------------- K6: intra-chunk Y via HMMA bf16x3 (D folded into M diag) ----------------
__global__ void __launch_bounds__(256) k_y(const float* __restrict__ Dp) {
    extern __shared__ bf16 sy[];
    bf16* sBh = sy;
    bf16* sBl = sy + 4608;
    bf16* sCh = sy + 2*4608;
    bf16* sCl = sy + 3*4608;
    bf16* sSh = sy + 4*4608;
    bf16* sSl = sy + 5*4608;
    __shared__ float sl[64], sdt[64], sw0;

    int bid = blockIdx.x;
    int c = bid & 31, h = (bid >> 5) & 7, b = bid >> 8;
    int tid = threadIdx.x;
    int t0 = b*LL + c*QC;
    float Dh = Dp[h];

    float lv = (tid < 64) ? g_dlog[(t0 + tid)*NH + h] : 0.f;
    if (tid < 64) sdt[tid] = g_dt[(t0 + tid)*NH + h];
    scan64(sl, &sw0, tid, lv);

    #pragma unroll
    for (int u = 0; u < 2; ++u) {
        int i = tid + u * 256;
        int r = i >> 3, c8 = (i & 7) << 3;
        size_t gs = (size_t)(t0 + r)*NST + c8;
        *(uint4*)(sBh + r*72 + c8) = *(const uint4*)(g_Bmh + gs);
        *(uint4*)(sBl + r*72 + c8) = *(const uint4*)(g_Bml + gs);
        *(uint4*)(sCh + r*72 + c8) = *(const uint4*)(g_Cmh + gs);
        *(uint4*)(sCl + r*72 + c8) = *(const uint4*)(g_Cml + gs);
        size_t ss = (size_t)bid*4096 + r*64 + c8;
        *(uint4*)(sSh + r*72 + c8) = *(const uint4*)(g_Sinh + ss);
        *(uint4*)(sSl + r*72 + c8) = *(const uint4*)(g_Sinl + ss);
    }
    __syncthreads();

    const int wid = tid >> 5, lane = tid & 31;
    const int wm = (wid >> 1) * 16, wn = (wid & 1) * 32;
    const int r0 = wm + (lane >> 2);

    float g[4][4], g3[4][4];
    #pragma unroll
    for (int i = 0; i < 4; i++)
        #pragma unroll
        for (int j = 0; j < 4; j++) { g[i][j] = 0.f; g3[i][j] = 0.f; }

    #pragma unroll
    for (int ks = 0; ks < 4; ++ks) {
        const int cc = ks * 16 + (lane & 3) * 2;
        uint32_t ah[4], al[4], bh[2], bl[2];
        lda(ah, sCh, r0, cc);
        lda(al, sCl, r0, cc);
        #pragma unroll
        for (int nf = 0; nf < 4; ++nf) {
            int nr = wn + nf * 8 + (lane >> 2);
            ldb(bh, sBh, nr, cc);  ldb(bl, sBl, nr, cc);
            mma16816(g[nf], ah, bh);
            mma16816(g[nf], ah, bl);
            mma16816(g[nf], al, bh);
            ldb(bh, sSh, nr, cc);  ldb(bl, sSl, nr, cc);
            mma16816(g3[nf], ah, bh);
            mma16816(g3[nf], ah, bl);
            mma16816(g3[nf], al, bh);
        }
    }
    __syncthreads();   // reuse sB for M, sS for X^T

    float Lr0 = sl[r0], Lr8 = sl[r0 + 8];
    #pragma unroll
    for (int nf = 0; nf < 4; ++nf) {
        int jn = wn + nf * 8 + (lane & 3) * 2;
        #pragma unroll
        for (int jj = 0; jj < 2; ++jj) {
            int j = jn + jj;
            float Lj = sl[j], dtj = sdt[j];
            float m0 = (r0     >= j) ? __expf(Lr0 - Lj) * dtj * g[nf][jj]     : 0.f;
            float m8 = (r0 + 8 >= j) ? __expf(Lr8 - Lj) * dtj * g[nf][2 + jj] : 0.f;
            if (r0 == j)     m0 += Dh;
            if (r0 + 8 == j) m8 += Dh;
            float h0 = rtbf(m0), h8 = rtbf(m8);
            sBh[r0*72 + j]     = __float2bfloat16(h0);
            sBl[r0*72 + j]     = __float2bfloat16(m0 - h0);
            sBh[(r0+8)*72 + j] = __float2bfloat16(h8);
            sBl[(r0+8)*72 + j] = __float2bfloat16(m8 - h8);
        }
    }
    #pragma unroll
    for (int u = 0; u < 4; ++u) {
        int i = tid + u * 256;
        int j = i >> 4, p4 = (i & 15) << 2;
        float4 vx = *(const float4*)(g_xact + (size_t)(t0 + j)*DIN + h*64 + p4);
        store4T(sSh, sSl, p4, j, vx);
    }
    __syncthreads();

    float Y[4][4];
    #pragma unroll
    for (int i = 0; i < 4; i++)
        #pragma unroll
        for (int j = 0; j < 4; j++) Y[i][j] = 0.f;
    #pragma unroll
    for (int ks = 0; ks < 4; ++ks) {
        const int cc = ks * 16 + (lane & 3) * 2;
        uint32_t ah[4], al[4], bh[2], bl[2];
        lda(ah, sBh, r0, cc);
        lda(al, sBl, r0, cc);
        #pragma unroll
        for (int nf = 0; nf < 4; ++nf) {
            int nr = wn + nf * 8 + (lane >> 2);
            ldb(bh, sSh, nr, cc);  ldb(bl, sSl, nr, cc);
            mma16816(Y[nf], ah, bh);
            mma16816(Y[nf], ah, bl);
            mma16816(Y[nf], al, bh);
        }
    }

    float e0 = __expf(Lr0), e8 = __expf(Lr8);
    #pragma unroll
    for (int nf = 0; nf < 4; ++nf) {
        int p0 = wn + nf * 8 + (lane & 3) * 2;
        #pragma unroll
        for (int jj = 0; jj < 2; ++jj) {
            int p = p0 + jj;
            float y0 = Y[nf][jj]     + e0 * g3[nf][jj];
            float y8 = Y[nf][2 + jj] + e8 * g3[nf][2 + jj];
            g_y[(size_t)(t0 + r0)*DIN     + h*64 + p] = y0;
            g_y[(size_t)(t0 + r0 + 8)*DIN + h*64 + p] = y8;
        }
    }
}
#define KY_DSMEM (6*4608*2)

// ---------------- K7: gating + RMSNorm; emits bf16 hi/lo ----------------
__global__ void __launch_bounds__(256) k_gate(const float* __restrict__ rmsw) {
    int row = blockIdx.x, t = threadIdx.x;
    float gv[2]; float ss = 0.f;
    #pragma unroll
    for (int k = 0; k < 2; k++) {
        int i = t + k*256;
        float z = g_zx[row*NPROJ + i];
        float v = g_y[row*DIN + i] * fsilu(z);
        gv[k] = v; ss += v*v;
    }
    #pragma unroll
    for (int o = 16; o; o >>= 1) ss += __shfl_xor_sync(0xffffffffu, ss, o);
    __shared__ float red[8];
    if ((t & 31) == 0) red[t>>5] = ss;
    __syncthreads();
    __shared__ float scale;
    if (t == 0) {
        float tot = 0.f;
        for (int i = 0; i < 8; i++) tot += red[i];
        scale = rsqrtf(tot/512.f + 1e-5f);
    }
    __syncthreads();
    #pragma unroll
    for (int k = 0; k < 2; k++) {
        int i = t + k*256;
        float v = gv[k] * scale * rmsw[i];
        float hi = rtbf(v);
        g_yh[row*DIN + i] = __float2bfloat16(hi);
        g_yl[row*DIN + i] = __float2bfloat16(v - hi);
    }
}

// ---------------- launch (single stream) ----------------
extern "C" void kernel_launch(void* const* d_in, const int* in_sizes, int n_in,
                              void* d_out, int out_size) {
    const float* hid   = (const float*)d_in[0];
    const float* normw = (const float*)d_in[1];
    const float* normb = (const float*)d_in[2];
    const float* Win   = (const float*)d_in[3];
    const float* convw = (const float*)d_in[4];
    const float* convb = (const float*)d_in[5];
    const float* dtb   = (const float*)d_in[6];
    const float* Alog  = (const float*)d_in[7];
    const float* Dp    = (const float*)d_in[8];
    const float* rmsw  = (const float*)d_in[9];
    const float* Wout  = (const float*)d_in[10];
    float* out   = (float*)d_out;
    float* resid = out + out_size/2;

    bf16 *winTh, *winTl, *woutTh, *woutTl;
    cudaGetSymbolAddress((void**)&winTh,  g_WinTh);
    cudaGetSymbolAddress((void**)&winTl,  g_WinTl);
    cudaGetSymbolAddress((void**)&woutTh, g_WoutTh);
    cudaGetSymbolAddress((void**)&woutTl, g_WoutTl);

    cudaFuncSetAttribute(k_tgemm_in,  cudaFuncAttributeMaxDynamicSharedMemorySize, TG_DSMEM);
    cudaFuncSetAttribute(k_tgemm_out, cudaFuncAttributeMaxDynamicSharedMemorySize, TG_DSMEM);
    cudaFuncSetAttribute(k_y,         cudaFuncAttributeMaxDynamicSharedMemorySize, KY_DSMEM);

    k_prep     <<<dim3(1280/32, DD/32), dim3(32, 8)>>>(Win, winTh, winTl, DD, NPROJ, 1280);
    k_prep     <<<dim3(DD/32, DIN/32),  dim3(32, 8)>>>(Wout, woutTh, woutTl, DIN, DD, DD);
    k_ln       <<<ROWS, 256>>>(hid, normw, normb, resid);
    k_tgemm_in <<<dim3((NPROJ + 63)/64, ROWS/128), 256, TG_DSMEM>>>();
    k_conv     <<<dim3(CDIM/128, LL/64, BB), 256>>>(convw, convb);
    k_dt       <<<ROWS*NH/256, 256>>>(dtb, Alog);
    k_cstate   <<<BB*NH*NC, 256>>>();
    k_seq      <<<BB*NH*4, 256>>>();
    k_y        <<<BB*NH*NC, 256, KY_DSMEM>>>(Dp);
    k_gate     <<<ROWS, 256>>>(rmsw);
    k_tgemm_out<<<dim3(DD/64, ROWS/128), 256, TG_DSMEM>>>(out);
}

// round 15
// speedup vs baseline: 1.5111x; 1.0388x over previous
#include <cuda_runtime.h>
#include <cuda_bf16.h>
#include <math.h>
#include <stdint.h>

// ---------------- problem constants ----------------
#define BB    2
#define LL    2048
#define DD    256
#define DIN   512
#define NH    8
#define NST   64
#define CDIM  640
#define NPROJ 1160
#define ROWS  (BB*LL)      // 4096
#define NC    32           // chunks per sequence
#define QC    64           // chunk length

typedef __nv_bfloat16 bf16;

// ---------------- scratch ----------------
__device__ __align__(16) bf16  g_xh    [ROWS*DD];
__device__ __align__(16) bf16  g_xl    [ROWS*DD];
__device__ __align__(16) float g_zx    [ROWS*NPROJ];
__device__ __align__(16) float g_xact  [ROWS*DIN];
__device__ __align__(16) bf16  g_Bmh   [ROWS*NST];
__device__ __align__(16) bf16  g_Bml   [ROWS*NST];
__device__ __align__(16) bf16  g_Cmh   [ROWS*NST];
__device__ __align__(16) bf16  g_Cml   [ROWS*NST];
__device__ __align__(16) float g_dt    [ROWS*NH];
__device__ __align__(16) float g_dlog  [ROWS*NH];
__device__ __align__(16) float g_chunkS[BB*NH*NC*QC*NST];
__device__ __align__(16) float g_lend  [BB*NH*NC];
__device__ __align__(16) bf16  g_Sinh  [BB*NH*NC*QC*NST];
__device__ __align__(16) bf16  g_Sinl  [BB*NH*NC*QC*NST];
__device__ __align__(16) float g_y     [ROWS*DIN];
__device__ __align__(16) bf16  g_yh    [ROWS*DIN];
__device__ __align__(16) bf16  g_yl    [ROWS*DIN];
__device__ __align__(16) bf16  g_WinTh [1280*DD];           // [n][k], N padded
__device__ __align__(16) bf16  g_WinTl [1280*DD];
__device__ __align__(16) bf16  g_WoutTh[DD*DIN];
__device__ __align__(16) bf16  g_WoutTl[DD*DIN];

__device__ __forceinline__ float fsilu(float x) {
    return __fdividef(x, 1.f + __expf(-x));
}

// ================= warp MMA helpers =================
__device__ __forceinline__ void mma16816(float* c, const uint32_t* a, const uint32_t* b) {
    asm volatile(
        "mma.sync.aligned.m16n8k16.row.col.f32.bf16.bf16.f32 "
        "{%0,%1,%2,%3}, {%4,%5,%6,%7}, {%8,%9}, {%0,%1,%2,%3};"
        : "+f"(c[0]), "+f"(c[1]), "+f"(c[2]), "+f"(c[3])
        : "r"(a[0]), "r"(a[1]), "r"(a[2]), "r"(a[3]), "r"(b[0]), "r"(b[1]));
}
__device__ __forceinline__ uint32_t pk(float a, float b) {
    __nv_bfloat162 t = __floats2bfloat162_rn(a, b);
    return *reinterpret_cast<uint32_t*>(&t);
}
__device__ __forceinline__ float rtbf(float v) {
    return __bfloat162float(__float2bfloat16(v));
}
__device__ __forceinline__ void store4T(bf16* sh, bf16* slo, int q4, int j, float4 v) {
    float f[4] = {v.x, v.y, v.z, v.w};
    #pragma unroll
    for (int k = 0; k < 4; k++) {
        float hi = rtbf(f[k]);
        sh [(q4 + k) * 72 + j] = __float2bfloat16(hi);
        slo[(q4 + k) * 72 + j] = __float2bfloat16(f[k] - hi);
    }
}
__device__ __forceinline__ void lda(uint32_t* a, const bf16* s, int r0, int c) {
    int o0 = r0 * 72 + c, o8 = o0 + 8 * 72;
    a[0] = *(const uint32_t*)(s + o0);
    a[1] = *(const uint32_t*)(s + o8);
    a[2] = *(const uint32_t*)(s + o0 + 8);
    a[3] = *(const uint32_t*)(s + o8 + 8);
}
__device__ __forceinline__ void ldb(uint32_t* b, const bf16* s, int n, int c) {
    int o = n * 72 + c;
    b[0] = *(const uint32_t*)(s + o);
    b[1] = *(const uint32_t*)(s + o + 8);
}
__device__ __forceinline__ void cpasync16(uint32_t saddr, const void* g) {
    asm volatile("cp.async.cg.shared.global [%0], [%1], 16;" :: "r"(saddr), "l"(g));
}
#define CP_COMMIT()  asm volatile("cp.async.commit_group;")
#define CP_WAIT(n)   asm volatile("cp.async.wait_group %0;" :: "n"(n))

// ---------------- K0: transpose + hi/lo split of weights ----------------
__global__ void k_prep(const float* __restrict__ W, bf16* __restrict__ Th,
                       bf16* __restrict__ Tl, int K, int N, int Npad) {
    __shared__ float t[32][33];
    int n0 = blockIdx.x * 32, k0 = blockIdx.y * 32;
    int tx = threadIdx.x, ty = threadIdx.y;
    #pragma unroll
    for (int i = 0; i < 4; i++) {
        int k = k0 + ty + i * 8;
        t[ty + i * 8][tx] = (n0 + tx < N) ? W[(size_t)k * N + n0 + tx] : 0.f;
    }
    __syncthreads();
    #pragma unroll
    for (int i = 0; i < 4; i++) {
        int n = n0 + ty + i * 8;
        if (n < Npad) {
            float v = t[tx][ty + i * 8];
            float hi = rtbf(v);
            Th[(size_t)n * K + k0 + tx] = __float2bfloat16(hi);
            Tl[(size_t)n * K + k0 + tx] = __float2bfloat16(v - hi);
        }
    }
}

// ======== pipelined GEMM (r7 config: K-panel 64, stride 72) ========
#define P_AH 0
#define P_AL (128*72)
#define P_BH (2*128*72)
#define P_BL (2*128*72 + 64*72)
#define P_ELEMS (2*128*72 + 2*64*72)
#define TG_DSMEM (2 * P_ELEMS * 2)      // 110592 B

__device__ __forceinline__ void load_panel(uint32_t sbuf,
                                           const bf16* __restrict__ Ah,
                                           const bf16* __restrict__ Al,
                                           const bf16* __restrict__ WTh,
                                           const bf16* __restrict__ WTl,
                                           int bm, int bn, int k0, int K, int tid) {
    #pragma unroll
    for (int u = 0; u < 4; ++u) {
        int i = tid + u * 256;
        int r = i >> 3, c8 = (i & 7) << 3;
        size_t src = (size_t)(bm + r) * K + k0 + c8;
        uint32_t doff = (uint32_t)((r * 72 + c8) * 2);
        cpasync16(sbuf + P_AH * 2 + doff, Ah + src);
        cpasync16(sbuf + P_AL * 2 + doff, Al + src);
    }
    #pragma unroll
    for (int u = 0; u < 2; ++u) {
        int i = tid + u * 256;
        int r = i >> 3, c8 = (i & 7) << 3;
        size_t src = (size_t)(bn + r) * K + k0 + c8;
        uint32_t doff = (uint32_t)((r * 72 + c8) * 2);
        cpasync16(sbuf + P_BH * 2 + doff, WTh + src);
        cpasync16(sbuf + P_BL * 2 + doff, WTl + src);
    }
}

__device__ __forceinline__ void tgemm_body(const bf16* __restrict__ Ah,
                                           const bf16* __restrict__ Al,
                                           const bf16* __restrict__ WTh,
                                           const bf16* __restrict__ WTl,
                                           float* __restrict__ C, int Nn, int K) {
    extern __shared__ bf16 sm[];
    const uint32_t sbase = (uint32_t)__cvta_generic_to_shared(sm);
    const int bm = blockIdx.y * 128;
    const int bn = blockIdx.x * 64;
    const int tid = threadIdx.x;
    const int wid = tid >> 5, lane = tid & 31;
    const int wm = (wid >> 1) * 32;
    const int wn = (wid & 1) * 32;

    float acc[2][4][4];
    #pragma unroll
    for (int i = 0; i < 2; i++)
        #pragma unroll
        for (int j = 0; j < 4; j++)
            #pragma unroll
            for (int k = 0; k < 4; k++) acc[i][j][k] = 0.f;

    const int NP = K >> 6;
    load_panel(sbase, Ah, Al, WTh, WTl, bm, bn, 0, K, tid);
    CP_COMMIT();

    for (int p = 0; p < NP; ++p) {
        if (p + 1 < NP) {
            load_panel(sbase + ((p + 1) & 1) * P_ELEMS * 2,
                       Ah, Al, WTh, WTl, bm, bn, (p + 1) << 6, K, tid);
            CP_COMMIT();
            CP_WAIT(1);
        } else {
            CP_WAIT(0);
        }
        __syncthreads();

        const bf16* buf = sm + (p & 1) * P_ELEMS;
        const bf16* sAh = buf + P_AH;
        const bf16* sAl = buf + P_AL;
        const bf16* sBh = buf + P_BH;
        const bf16* sBl = buf + P_BL;

        #pragma unroll
        for (int ks = 0; ks < 4; ++ks) {
            const int c = ks * 16 + (lane & 3) * 2;
            const int ra = wm + (lane >> 2);
            uint32_t ah[2][4], al[2][4], bh[4][2], bl[4][2];
            #pragma unroll
            for (int mf = 0; mf < 2; ++mf) {
                lda(ah[mf], sAh, ra + mf * 16, c);
                lda(al[mf], sAl, ra + mf * 16, c);
            }
            #pragma unroll
            for (int nf = 0; nf < 4; ++nf) {
                ldb(bh[nf], sBh, wn + nf * 8 + (lane >> 2), c);
                ldb(bl[nf], sBl, wn + nf * 8 + (lane >> 2), c);
            }
            #pragma unroll
            for (int mf = 0; mf < 2; ++mf)
                #pragma unroll
                for (int nf = 0; nf < 4; ++nf) {
                    mma16816(acc[mf][nf], ah[mf], bh[nf]);
                    mma16816(acc[mf][nf], ah[mf], bl[nf]);
                    mma16816(acc[mf][nf], al[mf], bh[nf]);
                }
        }
        __syncthreads();
    }

    #pragma unroll
    for (int mf = 0; mf < 2; ++mf) {
        int row0 = bm + wm + mf * 16 + (lane >> 2);
        #pragma unroll
        for (int nf = 0; nf < 4; ++nf) {
            int col = bn + wn + nf * 8 + (lane & 3) * 2;
            if (col < Nn) {
                float* p0 = C + (size_t)row0 * Nn + col;
                float* p1 = C + (size_t)(row0 + 8) * Nn + col;
                p0[0] = acc[mf][nf][0];
                if (col + 1 < Nn) p0[1] = acc[mf][nf][1];
                p1[0] = acc[mf][nf][2];
                if (col + 1 < Nn) p1[1] = acc[mf][nf][3];
            }
        }
    }
}

__global__ void __launch_bounds__(256) k_tgemm_in() {
    tgemm_body(g_xh, g_xl, g_WinTh, g_WinTl, g_zx, NPROJ, DD);
}
__global__ void __launch_bounds__(256) k_tgemm_out(float* __restrict__ out) {
    tgemm_body(g_yh, g_yl, g_WoutTh, g_WoutTl, out, DD, DIN);
}

// ---------------- K1: LayerNorm + residual copy ----------------
__global__ void __launch_bounds__(256) k_ln(const float* __restrict__ hid,
                                            const float* __restrict__ w,
                                            const float* __restrict__ b,
                                            float* __restrict__ resid) {
    int row = blockIdx.x, t = threadIdx.x;
    float v = hid[row*DD + t];
    float s = v, q = v*v;
    #pragma unroll
    for (int o = 16; o; o >>= 1) {
        s += __shfl_xor_sync(0xffffffffu, s, o);
        q += __shfl_xor_sync(0xffffffffu, q, o);
    }
    __shared__ float r1[8], r2[8];
    if ((t & 31) == 0) { r1[t>>5] = s; r2[t>>5] = q; }
    __syncthreads();
    __shared__ float smu, srs;
    if (t == 0) {
        float S = 0.f, Qs = 0.f;
        for (int i = 0; i < 8; i++) { S += r1[i]; Qs += r2[i]; }
        float mu = S / 256.f;
        smu = mu;
        srs = rsqrtf(Qs/256.f - mu*mu + 1e-5f);
    }
    __syncthreads();
    float xv = (v - smu) * srs * w[t] + b[t];
    float hi = rtbf(xv);
    g_xh[row*DD + t] = __float2bfloat16(hi);
    g_xl[row*DD + t] = __float2bfloat16(xv - hi);
    resid[row*DD + t] = v;
}

// ---------------- K3: conv via smem tile (1x global reads) + fused dt ----------------
// grid (6, LL/64, BB): cb<5 -> 128 channels x 64 L conv; cb==5 -> dt for these 64 rows
__global__ void __launch_bounds__(256) k_conv(const float* __restrict__ cw,
                                              const float* __restrict__ cb_,
                                              const float* __restrict__ dtb,
                                              const float* __restrict__ Alog) {
    __shared__ float st[67*128];
    int cbk = blockIdx.x;
    int b = blockIdx.z;
    int l0 = blockIdx.y * 64;
    int tid = threadIdx.x;

    if (cbk == 5) {
        // softplus(dt): 64 rows x 8 heads = 512 entries, 2 per thread
        #pragma unroll
        for (int k = 0; k < 2; k++) {
            int idx = tid + k * 256;
            int rl = idx >> 3, h = idx & 7;
            int row = b * LL + l0 + rl;
            float raw = g_zx[(size_t)row * NPROJ + 1152 + h] + dtb[h];
            float dt = (raw > 20.f) ? raw : log1pf(__expf(raw));
            g_dt[row*NH + h]   = dt;
            g_dlog[row*NH + h] = -dt * __expf(Alog[h]);
        }
        return;
    }

    int c0 = cbk * 128;
    // stage [67 rows (l0-3..l0+63)] x [128 channels]
    for (int i = tid; i < 67 * 128; i += 256) {
        int r = i >> 7, cc = i & 127;
        int l = l0 + r - 3;
        st[i] = (l >= 0) ? g_zx[(size_t)(b * LL + l) * NPROJ + 512 + c0 + cc] : 0.f;
    }
    __syncthreads();

    int c = c0 + (tid & 127);
    int cc = tid & 127;
    int lh = tid >> 7;
    float cw0 = cw[c*4], cw1 = cw[c*4+1], cw2 = cw[c*4+2], cw3 = cw[c*4+3];
    float bias = cb_[c];

    #pragma unroll 4
    for (int i = 0; i < 32; ++i) {
        int l = lh * 32 + i;                // local 0..63
        float acc = bias + cw0 * st[l*128 + cc]       + cw1 * st[(l+1)*128 + cc]
                         + cw2 * st[(l+2)*128 + cc]   + cw3 * st[(l+3)*128 + cc];
        float sv = fsilu(acc);
        int row = b * LL + l0 + l;
        if (c < DIN) {
            g_xact[(size_t)row * DIN + c] = sv;
        } else if (c < DIN + NST) {
            float hi = rtbf(sv);
            g_Bmh[(size_t)row * NST + (c - DIN)] = __float2bfloat16(hi);
            g_Bml[(size_t)row * NST + (c - DIN)] = __float2bfloat16(sv - hi);
        } else {
            float hi = rtbf(sv);
            g_Cmh[(size_t)row * NST + (c - DIN - NST)] = __float2bfloat16(hi);
            g_Cml[(size_t)row * NST + (c - DIN - NST)] = __float2bfloat16(sv - hi);
        }
    }
}

// ---- inclusive warp-scan of 64 values ----
__device__ __forceinline__ void scan64(float* sl, float* sw0tot, int tid, float v) {
    if (tid < 64) {
        #pragma unroll
        for (int o = 1; o < 32; o <<= 1) {
            float n = __shfl_up_sync(0xffffffffu, v, o);
            if ((tid & 31) >= o) v += n;
        }
        sl[tid] = v;
        if (tid == 31) *sw0tot = v;
    }
    __syncthreads();
    if (tid >= 32 && tid < 64) sl[tid] += *sw0tot;
    __syncthreads();
}

// ---------------- K4: per-chunk partial state via HMMA bf16x3 ----------------
__global__ void __launch_bounds__(256) k_cstate() {
    __shared__ bf16 sXh[64*72], sXl[64*72], sBTh[64*72], sBTl[64*72];
    __shared__ float sl[64], scoef[64], sw0;
    int bid = blockIdx.x;
    int c = bid & 31, h = (bid >> 5) & 7, b = bid >> 8;
    int tid = threadIdx.x;
    int t0 = b*LL + c*QC;

    float lv = (tid < 64) ? g_dlog[(t0 + tid)*NH + h] : 0.f;
    scan64(sl, &sw0, tid, lv);
    float lend = sl[63];
    if (tid < 64) scoef[tid] = __expf(lend - sl[tid]) * g_dt[(t0 + tid)*NH + h];
    if (tid == 0) g_lend[bid] = lend;
    __syncthreads();

    #pragma unroll
    for (int u = 0; u < 4; ++u) {
        int i = tid + u * 256;
        int j = i >> 4, n4 = (i & 15) << 2;
        float cf = scoef[j];
        float4 vx = *(const float4*)(g_xact + (size_t)(t0 + j)*DIN + h*64 + n4);
        vx.x *= cf; vx.y *= cf; vx.z *= cf; vx.w *= cf;
        store4T(sXh, sXl, n4, j, vx);
        uint2 bh2 = *(const uint2*)(g_Bmh + (size_t)(t0 + j)*NST + n4);
        uint2 bl2 = *(const uint2*)(g_Bml + (size_t)(t0 + j)*NST + n4);
        const bf16* ph = (const bf16*)&bh2;
        const bf16* pl = (const bf16*)&bl2;
        #pragma unroll
        for (int k = 0; k < 4; k++) {
            sBTh[(n4 + k)*72 + j] = ph[k];
            sBTl[(n4 + k)*72 + j] = pl[k];
        }
    }
    __syncthreads();

    const int wid = tid >> 5, lane = tid & 31;
    const int wm = (wid >> 1) * 16, wn = (wid & 1) * 32;
    const int r0 = wm + (lane >> 2);
    float acc[4][4];
    #pragma unroll
    for (int i = 0; i < 4; i++)
        #pragma unroll
        for (int j = 0; j < 4; j++) acc[i][j] = 0.f;

    #pragma unroll
    for (int ks = 0; ks < 4; ++ks) {
        const int cc = ks * 16 + (lane & 3) * 2;
        uint32_t ah[4], al[4], bh[4][2], bl[4][2];
        lda(ah, sXh, r0, cc);
        lda(al, sXl, r0, cc);
        #pragma unroll
        for (int nf = 0; nf < 4; ++nf) {
            ldb(bh[nf], sBTh, wn + nf * 8 + (lane >> 2), cc);
            ldb(bl[nf], sBTl, wn + nf * 8 + (lane >> 2), cc);
        }
        #pragma unroll
        for (int nf = 0; nf < 4; ++nf) {
            mma16816(acc[nf], ah, bh[nf]);
            mma16816(acc[nf], ah, bl[nf]);
            mma16816(acc[nf], al, bh[nf]);
        }
    }

    float* op = g_chunkS + (size_t)bid * 4096;
    #pragma unroll
    for (int nf = 0; nf < 4; ++nf) {
        int n0 = wn + nf * 8 + (lane & 3) * 2;
        op[r0*64 + n0]     = acc[nf][0]; op[r0*64 + n0 + 1]     = acc[nf][1];
        op[(r0+8)*64 + n0] = acc[nf][2]; op[(r0+8)*64 + n0 + 1] = acc[nf][3];
    }
}

// ---------------- K5: inter-chunk recurrence, batched prefetch (MLP 8) ----------------
__global__ void __launch_bounds__(256) k_seq() {
    __shared__ float sa[NC];
    int bh = blockIdx.x >> 2, part = blockIdx.x & 3, tid = threadIdx.x;
    if (tid < NC) sa[tid] = __expf(g_lend[bh*NC + tid]);
    __syncthreads();
    int e = (part * 256 + tid) * 4;
    size_t base0 = (size_t)bh * NC * 4096 + e;
    float4 s = make_float4(0.f, 0.f, 0.f, 0.f);
    for (int cb = 0; cb < NC; cb += 8) {
        float4 v[8];
        #pragma unroll
        for (int k = 0; k < 8; k++)
            v[k] = *(const float4*)(g_chunkS + base0 + (size_t)(cb + k) * 4096);
        #pragma unroll
        for (int k = 0; k < 8; k++) {
            size_t off = base0 + (size_t)(cb + k) * 4096;
            float h0 = rtbf(s.x), h1 = rtbf(s.y), h2 = rtbf(s.z), h3 = rtbf(s.w);
            *(uint2*)(g_Sinh + off) = make_uint2(pk(h0, h1), pk(h2, h3));
            *(uint2*)(g_Sinl + off) = make_uint2(pk(s.x - h0, s.y - h1), pk(s.z - h2, s.w - h3));
            float a = sa[cb + k];
            s.x = s.x*a + v[k].x; s.y = s.y*a + v[k].y;
            s.z = s.z*a + v[k].z; s.w = s.w*a + v[k].w;
        }
    }
}

// ---------------- K6: intra-chunk Y via HMMA bf16x3 (D folded into M diag) ----------------
__global__ void __launch_bounds__(256) k_y(const float* __restrict__ Dp) {
    extern __shared__ bf16 sy[];
    bf16* sBh = sy;
    bf16* sBl = sy + 4608;
    bf16* sCh = sy + 2*4608;
    bf16* sCl = sy + 3*4608;
    bf16* sSh = sy + 4*4608;
    bf16* sSl = sy + 5*4608;
    __shared__ float sl[64], sdt[64], sw0;

    int bid = blockIdx.x;
    int c = bid & 31, h = (bid >> 5) & 7, b = bid >> 8;
    int tid = threadIdx.x;
    int t0 = b*LL + c*QC;
    float Dh = Dp[h];

    float lv = (tid < 64) ? g_dlog[(t0 + tid)*NH + h] : 0.f;
    if (tid < 64) sdt[tid] = g_dt[(t0 + tid)*NH + h];
    scan64(sl, &sw0, tid, lv);

    #pragma unroll
    for (int u = 0; u < 2; ++u) {
        int i = tid + u * 256;
        int r = i >> 3, c8 = (i & 7) << 3;
        size_t gs = (size_t)(t0 + r)*NST + c8;
        *(uint4*)(sBh + r*72 + c8) = *(const uint4*)(g_Bmh + gs);
        *(uint4*)(sBl + r*72 + c8) = *(const uint4*)(g_Bml + gs);
        *(uint4*)(sCh + r*72 + c8) = *(const uint4*)(g_Cmh + gs);
        *(uint4*)(sCl + r*72 + c8) = *(const uint4*)(g_Cml + gs);
        size_t ss = (size_t)bid*4096 + r*64 + c8;
        *(uint4*)(sSh + r*72 + c8) = *(const uint4*)(g_Sinh + ss);
        *(uint4*)(sSl + r*72 + c8) = *(const uint4*)(g_Sinl + ss);
    }
    __syncthreads();

    const int wid = tid >> 5, lane = tid & 31;
    const int wm = (wid >> 1) * 16, wn = (wid & 1) * 32;
    const int r0 = wm + (lane >> 2);

    float g[4][4], g3[4][4];
    #pragma unroll
    for (int i = 0; i < 4; i++)
        #pragma unroll
        for (int j = 0; j < 4; j++) { g[i][j] = 0.f; g3[i][j] = 0.f; }

    #pragma unroll
    for (int ks = 0; ks < 4; ++ks) {
        const int cc = ks * 16 + (lane & 3) * 2;
        uint32_t ah[4], al[4], bh[2], bl[2];
        lda(ah, sCh, r0, cc);
        lda(al, sCl, r0, cc);
        #pragma unroll
        for (int nf = 0; nf < 4; ++nf) {
            int nr = wn + nf * 8 + (lane >> 2);
            ldb(bh, sBh, nr, cc);  ldb(bl, sBl, nr, cc);
            mma16816(g[nf], ah, bh);
            mma16816(g[nf], ah, bl);
            mma16816(g[nf], al, bh);
            ldb(bh, sSh, nr, cc);  ldb(bl, sSl, nr, cc);
            mma16816(g3[nf], ah, bh);
            mma16816(g3[nf], ah, bl);
            mma16816(g3[nf], al, bh);
        }
    }
    __syncthreads();   // reuse sB for M, sS for X^T

    float Lr0 = sl[r0], Lr8 = sl[r0 + 8];
    #pragma unroll
    for (int nf = 0; nf < 4; ++nf) {
        int jn = wn + nf * 8 + (lane & 3) * 2;
        #pragma unroll
        for (int jj = 0; jj < 2; ++jj) {
            int j = jn + jj;
            float Lj = sl[j], dtj = sdt[j];
            float m0 = (r0     >= j) ? __expf(Lr0 - Lj) * dtj * g[nf][jj]     : 0.f;
            float m8 = (r0 + 8 >= j) ? __expf(Lr8 - Lj) * dtj * g[nf][2 + jj] : 0.f;
            if (r0 == j)     m0 += Dh;
            if (r0 + 8 == j) m8 += Dh;
            float h0 = rtbf(m0), h8 = rtbf(m8);
            sBh[r0*72 + j]     = __float2bfloat16(h0);
            sBl[r0*72 + j]     = __float2bfloat16(m0 - h0);
            sBh[(r0+8)*72 + j] = __float2bfloat16(h8);
            sBl[(r0+8)*72 + j] = __float2bfloat16(m8 - h8);
        }
    }
    #pragma unroll
    for (int u = 0; u < 4; ++u) {
        int i = tid + u * 256;
        int j = i >> 4, p4 = (i & 15) << 2;
        float4 vx = *(const float4*)(g_xact + (size_t)(t0 + j)*DIN + h*64 + p4);
        store4T(sSh, sSl, p4, j, vx);
    }
    __syncthreads();

    float Y[4][4];
    #pragma unroll
    for (int i = 0; i < 4; i++)
        #pragma unroll
        for (int j = 0; j < 4; j++) Y[i][j] = 0.f;
    #pragma unroll
    for (int ks = 0; ks < 4; ++ks) {
        const int cc = ks * 16 + (lane & 3) * 2;
        uint32_t ah[4], al[4], bh[2], bl[2];
        lda(ah, sBh, r0, cc);
        lda(al, sBl, r0, cc);
        #pragma unroll
        for (int nf = 0; nf < 4; ++nf) {
            int nr = wn + nf * 8 + (lane >> 2);
            ldb(bh, sSh, nr, cc);  ldb(bl, sSl, nr, cc);
            mma16816(Y[nf], ah, bh);
            mma16816(Y[nf], ah, bl);
            mma16816(Y[nf], al, bh);
        }
    }

    float e0 = __expf(Lr0), e8 = __expf(Lr8);
    #pragma unroll
    for (int nf = 0; nf < 4; ++nf) {
        int p0 = wn + nf * 8 + (lane & 3) * 2;
        #pragma unroll
        for (int jj = 0; jj < 2; ++jj) {
            int p = p0 + jj;
            float y0 = Y[nf][jj]     + e0 * g3[nf][jj];
            float y8 = Y[nf][2 + jj] + e8 * g3[nf][2 + jj];
            g_y[(size_t)(t0 + r0)*DIN     + h*64 + p] = y0;
            g_y[(size_t)(t0 + r0 + 8)*DIN + h*64 + p] = y8;
        }
    }
}
#define KY_DSMEM (6*4608*2)

// ---------------- K7: gating + RMSNorm; emits bf16 hi/lo ----------------
__global__ void __launch_bounds__(256) k_gate(const float* __restrict__ rmsw) {
    int row = blockIdx.x, t = threadIdx.x;
    float gv[2]; float ss = 0.f;
    #pragma unroll
    for (int k = 0; k < 2; k++) {
        int i = t + k*256;
        float z = g_zx[row*NPROJ + i];
        float v = g_y[row*DIN + i] * fsilu(z);
        gv[k] = v; ss += v*v;
    }
    #pragma unroll
    for (int o = 16; o; o >>= 1) ss += __shfl_xor_sync(0xffffffffu, ss, o);
    __shared__ float red[8];
    if ((t & 31) == 0) red[t>>5] = ss;
    __syncthreads();
    __shared__ float scale;
    if (t == 0) {
        float tot = 0.f;
        for (int i = 0; i < 8; i++) tot += red[i];
        scale = rsqrtf(tot/512.f + 1e-5f);
    }
    __syncthreads();
    #pragma unroll
    for (int k = 0; k < 2; k++) {
        int i = t + k*256;
        float v = gv[k] * scale * rmsw[i];
        float hi = rtbf(v);
        g_yh[row*DIN + i] = __float2bfloat16(hi);
        g_yl[row*DIN + i] = __float2bfloat16(v - hi);
    }
}

// ---------------- launch (single stream) ----------------
extern "C" void kernel_launch(void* const* d_in, const int* in_sizes, int n_in,
                              void* d_out, int out_size) {
    const float* hid   = (const float*)d_in[0];
    const float* normw = (const float*)d_in[1];
    const float* normb = (const float*)d_in[2];
    const float* Win   = (const float*)d_in[3];
    const float* convw = (const float*)d_in[4];
    const float* convb = (const float*)d_in[5];
    const float* dtb   = (const float*)d_in[6];
    const float* Alog  = (const float*)d_in[7];
    const float* Dp    = (const float*)d_in[8];
    const float* rmsw  = (const float*)d_in[9];
    const float* Wout  = (const float*)d_in[10];
    float* out   = (float*)d_out;
    float* resid = out + out_size/2;

    bf16 *winTh, *winTl, *woutTh, *woutTl;
    cudaGetSymbolAddress((void**)&winTh,  g_WinTh);
    cudaGetSymbolAddress((void**)&winTl,  g_WinTl);
    cudaGetSymbolAddress((void**)&woutTh, g_WoutTh);
    cudaGetSymbolAddress((void**)&woutTl, g_WoutTl);

    cudaFuncSetAttribute(k_tgemm_in,  cudaFuncAttributeMaxDynamicSharedMemorySize, TG_DSMEM);
    cudaFuncSetAttribute(k_tgemm_out, cudaFuncAttributeMaxDynamicSharedMemorySize, TG_DSMEM);
    cudaFuncSetAttribute(k_y,         cudaFuncAttributeMaxDynamicSharedMemorySize, KY_DSMEM);

    k_prep     <<<dim3(1280/32, DD/32), dim3(32, 8)>>>(Win, winTh, winTl, DD, NPROJ, 1280);
    k_prep     <<<dim3(DD/32, DIN/32),  dim3(32, 8)>>>(Wout, woutTh, woutTl, DIN, DD, DD);
    k_ln       <<<ROWS, 256>>>(hid, normw, normb, resid);
    k_tgemm_in <<<dim3((NPROJ + 63)/64, ROWS/128), 256, TG_DSMEM>>>();
    k_conv     <<<dim3(6, LL/64, BB), 256>>>(convw, convb, dtb, Alog);
    k_cstate   <<<BB*NH*NC, 256>>>();
    k_seq      <<<BB*NH*4, 256>>>();
    k_y        <<<BB*NH*NC, 256, KY_DSMEM>>>(Dp);
    k_gate     <<<ROWS, 256>>>(rmsw);
    k_tgemm_out<<<dim3(DD/64, ROWS/128), 256, TG_DSMEM>>>(out);
}